// round 7
// baseline (speedup 1.0000x reference)
#include <cuda_runtime.h>

#define C 256
#define H 8
#define NUM_DST 256
#define NMAX 50000
#define EMAX 300000
#define LISTCAP 8192
#define HB 512            // histogram/scatter blocks
#define INV_SQRT_DH 0.17677669529663687f
#define LN_EPS 1e-5f
#define AW 4              // warps per attention block
#define AT (AW * 32)

typedef unsigned long long u64;

__device__ int g_deg[NMAX];
__device__ int g_bcount[NUM_DST];
__device__ int g_bstart[NUM_DST];
__device__ int g_blockhist[HB * NUM_DST];
__device__ int g_blockbase[HB * NUM_DST];
__device__ int g_listcount;
__device__ int g_list[LISTCAP];
__device__ unsigned char g_spd[EMAX];
__device__ int g_sedge[EMAX];        // packed: src | (spd << 16), dst-bucket order
__device__ float g_u[NUM_DST * H * C];
__device__ float g_c0[NUM_DST * H];
__device__ float g_outsmall[NUM_DST * C];

// ---- f32x2 packed helpers --------------------------------------------------
__device__ __forceinline__ u64 pack2(float lo, float hi) {
    u64 r; asm("mov.b64 %0, {%1, %2};" : "=l"(r) : "f"(lo), "f"(hi)); return r;
}
__device__ __forceinline__ void unpack2(u64 v, float& lo, float& hi) {
    asm("mov.b64 {%0, %1}, %2;" : "=f"(lo), "=f"(hi) : "l"(v));
}
__device__ __forceinline__ void fma2(u64& d, u64 a, u64 b) {
    asm("fma.rn.f32x2 %0, %1, %2, %3;" : "=l"(d) : "l"(a), "l"(b), "l"(d));
}

// ---------------------------------------------------------------------------
// K0: init (deg + list counter only; spd handled inside k_bfs)
__global__ void k_init(int n) {
    int i = blockIdx.x * blockDim.x + threadIdx.x;
    if (i < n) g_deg[i] = 0;
    if (i == 0) g_listcount = 0;
}

// ---------------------------------------------------------------------------
// K1: block-local histograms + out-degree + src<256 list
__global__ void k_hist(const int* __restrict__ src, const int* __restrict__ dst, int e) {
    __shared__ int hist[NUM_DST];
    int t = threadIdx.x;
    hist[t] = 0;
    __syncthreads();
    for (int i = blockIdx.x * blockDim.x + t; i < e; i += gridDim.x * blockDim.x) {
        int s = src[i], d = dst[i];
        atomicAdd(&g_deg[s], 1);
        atomicAdd(&hist[d], 1);
        if (s < NUM_DST) {
            int p = atomicAdd(&g_listcount, 1);
            if (p < LISTCAP) g_list[p] = i;
        }
    }
    __syncthreads();
    g_blockhist[blockIdx.x * NUM_DST + t] = hist[t];
}

// ---------------------------------------------------------------------------
// K2: bucket totals, global scan, per-block bases, in-degree fold
__global__ void k_prefix() {
    __shared__ int tmp[NUM_DST];
    int t = threadIdx.x;
    int total = 0;
    for (int b = 0; b < HB; b++) total += g_blockhist[b * NUM_DST + t];
    tmp[t] = total;
    __syncthreads();
    for (int off = 1; off < NUM_DST; off <<= 1) {
        int v = (t >= off) ? tmp[t - off] : 0;
        __syncthreads();
        tmp[t] += v;
        __syncthreads();
    }
    int excl = tmp[t] - total;
    g_bstart[t] = excl;
    g_bcount[t] = total;
    g_deg[t] += total;  // in-degree (all dst < 256)
    int run = excl;
    for (int b = 0; b < HB; b++) {
        g_blockbase[b * NUM_DST + t] = run;
        run += g_blockhist[b * NUM_DST + t];
    }
}

// ---------------------------------------------------------------------------
// K3: reverse-BFS spd buckets. Initializes g_spd for listed edges itself.
__global__ void k_bfs(const int* __restrict__ src, const int* __restrict__ dst) {
    __shared__ unsigned F0[NUM_DST][8];
    __shared__ unsigned F1[NUM_DST][8];
    int t = threadIdx.x;
    #pragma unroll
    for (int w = 0; w < 8; w++)
        F0[t][w] = (w == (t >> 5)) ? (1u << (t & 31)) : 0u;
    int cnt = g_listcount;
    if (cnt > LISTCAP) cnt = LISTCAP;
    for (int i = t; i < cnt; i += 256) g_spd[g_list[i]] = 4;  // MAX_SPD+1
    __syncthreads();
    for (int k = 1; k <= 3; k++) {
        #pragma unroll
        for (int w = 0; w < 8; w++) F1[t][w] = 0u;
        __syncthreads();
        for (int i = t; i < cnt; i += 256) {
            int e = g_list[i];
            int s = src[e], d = dst[e];
            #pragma unroll
            for (int w = 0; w < 8; w++) {
                unsigned v = F0[s][w];
                if (v) atomicOr(&F1[d][w], v);
            }
        }
        __syncthreads();
        for (int i = t; i < cnt; i += 256) {
            int e = g_list[i];
            int s = src[e], d = dst[e];
            if (g_spd[e] == 4 && ((F1[s][d >> 5] >> (d & 31)) & 1u))
                g_spd[e] = (unsigned char)k;
        }
        __syncthreads();
        #pragma unroll
        for (int w = 0; w < 8; w++) F0[t][w] = F1[t][w];
        __syncthreads();
    }
}

// ---------------------------------------------------------------------------
// K4: scatter with smem cursors; packs (src, spd) into one int
__global__ void k_scatter(const int* __restrict__ src, const int* __restrict__ dst, int e) {
    __shared__ int cur[NUM_DST];
    int t = threadIdx.x;
    cur[t] = g_blockbase[blockIdx.x * NUM_DST + t];
    __syncthreads();
    for (int i = blockIdx.x * blockDim.x + t; i < e; i += gridDim.x * blockDim.x) {
        int s = src[i], d = dst[i];
        int p = atomicAdd(&cur[d], 1);
        int sp = (s < NUM_DST) ? (int)g_spd[i] : 4;
        g_sedge[p] = s | (sp << 16);   // s < 50000 < 2^16
    }
}

// ---------------------------------------------------------------------------
// K5: per-dst u/c0 precompute, pre-scaled by 1/sqrt(DH)
__global__ void k_qu(const float* __restrict__ x,
                     const float* __restrict__ Wq, const float* __restrict__ bq,
                     const float* __restrict__ Wk, const float* __restrict__ bk) {
    int d = blockIdx.x;
    int t = threadIdx.x, lane = t & 31, wp = t >> 5;
    __shared__ float xs[C], qs[C];
    xs[t] = x[d * C + t];
    __syncthreads();
    for (int j = wp; j < C; j += 8) {
        const float* wr = Wq + j * C;
        float p = 0.f;
        #pragma unroll
        for (int i = 0; i < 8; i++) p += wr[lane + 32 * i] * xs[lane + 32 * i];
        #pragma unroll
        for (int o = 16; o; o >>= 1) p += __shfl_xor_sync(0xffffffffu, p, o);
        if (lane == 0) qs[j] = p + bq[j];
    }
    __syncthreads();
    #pragma unroll
    for (int h = 0; h < H; h++) {
        float acc = 0.f;
        #pragma unroll 8
        for (int j = 0; j < 32; j++)
            acc += qs[h * 32 + j] * Wk[(h * 32 + j) * C + t];
        g_u[d * H * C + h * C + t] = acc * INV_SQRT_DH;
    }
    if (t < H) {
        float s = 0.f;
        #pragma unroll
        for (int j = 0; j < 32; j++) s += qs[t * 32 + j] * bk[t * 32 + j];
        g_c0[d * H + t] = s * INV_SQRT_DH;
    }
}

// ---------------------------------------------------------------------------
// K6: per-dst fused attention. u held in REGISTERS (zero smem traffic in the
// edge loop). No online max (scores bounded). STS+tree-reduce epilogue (no
// smem atomics). f32x2 packed FMAs throughout.
__global__ __launch_bounds__(AT, 2)
void k_attn(const float* __restrict__ x,
            const float* __restrict__ Wv, const float* __restrict__ bv,
            const float* __restrict__ spd_w) {
    int d = blockIdx.x;
    int t = threadIdx.x, lane = t & 31, wp = t >> 5;
    __shared__ __align__(16) float scratch[AW][H * C];  // 32 KB; scratch[0] aliases final agg
    __shared__ float csw[5 * H];
    __shared__ float lsh2[AW * H];
    __shared__ float Linv[H];

    if (t < 40) csw[t] = g_c0[d * H + (t & 7)] + spd_w[t];

    // u[d] into registers: 8 heads x 8 channels per lane (64 regs)
    u64 ur[H][4];
    const float* ubase = g_u + d * (H * C) + lane * 8;
    #pragma unroll
    for (int h = 0; h < H; h++) {
        ulonglong2 p0 = *(const ulonglong2*)(ubase + h * C);
        ulonglong2 p1 = *(const ulonglong2*)(ubase + h * C + 4);
        ur[h][0] = p0.x; ur[h][1] = p0.y; ur[h][2] = p1.x; ur[h][3] = p1.y;
    }
    __syncthreads();

    int start = g_bstart[d], cnt = g_bcount[d];
    if (cnt == 0) {
        for (int i = t; i < C; i += AT) g_outsmall[d * C + i] = 0.f;
        return;
    }
    int end = start + cnt;
    int myh = (lane >> 2) & 7;
    unsigned b4 = (lane >> 4) & 1, b3 = (lane >> 3) & 1, b2 = (lane >> 2) & 1;

    u64 acc2[H][4];
    #pragma unroll
    for (int h = 0; h < H; h++)
        #pragma unroll
        for (int j = 0; j < 4; j++) acc2[h][j] = 0ull;
    float lsum = 0.f;

    int i = start + wp;
    int v = (i < end) ? g_sedge[i] : 0;

    for (; i < end; i += AW) {
        int s = v & 0xFFFF;
        int sp = v >> 16;
        if (i + AW < end) v = g_sedge[i + AW];

        const float4* xr = (const float4*)(x + s * C) + lane * 2;
        float4 a = xr[0];
        float4 b = xr[1];
        u64 xv2[4];
        xv2[0] = pack2(a.x, a.y); xv2[1] = pack2(a.z, a.w);
        xv2[2] = pack2(b.x, b.y); xv2[3] = pack2(b.z, b.w);

        // per-head partial dot over this lane's 8 channels (register u)
        float p[H];
        #pragma unroll
        for (int h = 0; h < H; h++) {
            u64 q2 = 0ull;
            fma2(q2, xv2[0], ur[h][0]);
            fma2(q2, xv2[1], ur[h][1]);
            fma2(q2, xv2[2], ur[h][2]);
            fma2(q2, xv2[3], ur[h][3]);
            float lo, hi; unpack2(q2, lo, hi);
            p[h] = lo + hi;
        }

        // head-folding butterfly: 9 shfls total
        float r4[4];
        #pragma unroll
        for (int j = 0; j < 4; j++) {
            float mine = b4 ? p[j + 4] : p[j];
            float send = b4 ? p[j] : p[j + 4];
            r4[j] = mine + __shfl_xor_sync(0xffffffffu, send, 16);
        }
        float r2[2];
        #pragma unroll
        for (int j = 0; j < 2; j++) {
            float mine = b3 ? r4[j + 2] : r4[j];
            float send = b3 ? r4[j] : r4[j + 2];
            r2[j] = mine + __shfl_xor_sync(0xffffffffu, send, 8);
        }
        {
            float mine = b2 ? r2[1] : r2[0];
            float send = b2 ? r2[0] : r2[1];
            r2[0] = mine + __shfl_xor_sync(0xffffffffu, send, 4);
        }
        r2[0] += __shfl_xor_sync(0xffffffffu, r2[0], 2);
        r2[0] += __shfl_xor_sync(0xffffffffu, r2[0], 1);
        // lane holds full score for head myh

        float wv = __expf(r2[0] + csw[sp * H + myh]);
        lsum += wv;

        #pragma unroll
        for (int h = 0; h < H; h++) {
            float wh = __shfl_sync(0xffffffffu, wv, h * 4);
            u64 w2 = pack2(wh, wh);
            fma2(acc2[h][0], w2, xv2[0]);
            fma2(acc2[h][1], w2, xv2[1]);
            fma2(acc2[h][2], w2, xv2[2]);
            fma2(acc2[h][3], w2, xv2[3]);
        }
    }

    // epilogue: plain STS + tree reduce (no atomics)
    #pragma unroll
    for (int h = 0; h < H; h++) {
        u64* dp = (u64*)&scratch[wp][h * C + lane * 8];
        dp[0] = acc2[h][0]; dp[1] = acc2[h][1];
        dp[2] = acc2[h][2]; dp[3] = acc2[h][3];
    }
    if ((lane & 3) == 0) lsh2[wp * H + myh] = lsum;
    __syncthreads();
    if (t < H) {
        float L = 0.f;
        #pragma unroll
        for (int w = 0; w < AW; w++) L += lsh2[w * H + t];
        Linv[t] = 1.f / L;
    }
    __syncthreads();
    for (int idx = t; idx < H * C; idx += AT) {
        float s = scratch[0][idx];
        #pragma unroll
        for (int w = 1; w < AW; w++) s += scratch[w][idx];
        scratch[0][idx] = s * Linv[idx >> 8];
    }
    __syncthreads();

    // out[c] = agg[c/32] . Wv[c,:] + bv[c] ; 4 warps x 64 outputs
    for (int r = 0; r < C / AW; r++) {
        int c = wp * (C / AW) + r;
        int h = c >> 5;
        const float4* wr = (const float4*)(Wv + c * C) + lane * 2;
        float4 wa = wr[0], wb = wr[1];
        const float* ar = &scratch[0][h * C + lane * 8];
        float pacc = wa.x * ar[0] + wa.y * ar[1] + wa.z * ar[2] + wa.w * ar[3]
                   + wb.x * ar[4] + wb.y * ar[5] + wb.z * ar[6] + wb.w * ar[7];
        #pragma unroll
        for (int o = 16; o; o >>= 1) pacc += __shfl_xor_sync(0xffffffffu, pacc, o);
        if (lane == 0) g_outsmall[d * C + c] = pacc + bv[c];
    }
}

// ---------------------------------------------------------------------------
// K7: residual + degree + LayerNorm, one warp per row
__global__ void k_ln(const float* __restrict__ x,
                     const float* __restrict__ gamma, const float* __restrict__ beta,
                     float* __restrict__ out, int n) {
    int row = blockIdx.x * 8 + (threadIdx.x >> 5);
    int lane = threadIdx.x & 31;
    if (row >= n) return;
    const float* xr = x + (size_t)row * C + lane * 8;
    float4 a = *(const float4*)(xr);
    float4 b = *(const float4*)(xr + 4);
    float v[8] = {a.x, a.y, a.z, a.w, b.x, b.y, b.z, b.w};
    float degf = (float)g_deg[row];
    #pragma unroll
    for (int j = 0; j < 8; j++) v[j] += degf;
    if (row < NUM_DST) {
        const float* orow = g_outsmall + row * C + lane * 8;
        float4 oa = *(const float4*)(orow);
        float4 ob = *(const float4*)(orow + 4);
        v[0] += oa.x; v[1] += oa.y; v[2] += oa.z; v[3] += oa.w;
        v[4] += ob.x; v[5] += ob.y; v[6] += ob.z; v[7] += ob.w;
    }
    float s = 0.f;
    #pragma unroll
    for (int j = 0; j < 8; j++) s += v[j];
    #pragma unroll
    for (int o = 16; o; o >>= 1) s += __shfl_xor_sync(0xffffffffu, s, o);
    float mu = s * (1.f / C);
    float q = 0.f;
    #pragma unroll
    for (int j = 0; j < 8; j++) { float dd = v[j] - mu; q += dd * dd; }
    #pragma unroll
    for (int o = 16; o; o >>= 1) q += __shfl_xor_sync(0xffffffffu, q, o);
    float rstd = rsqrtf(q * (1.f / C) + LN_EPS);
    const float* gr = gamma + lane * 8;
    const float* br = beta + lane * 8;
    float4 g1 = *(const float4*)(gr);
    float4 g2 = *(const float4*)(gr + 4);
    float4 b1 = *(const float4*)(br);
    float4 b2 = *(const float4*)(br + 4);
    float gv[8] = {g1.x, g1.y, g1.z, g1.w, g2.x, g2.y, g2.z, g2.w};
    float bvv[8] = {b1.x, b1.y, b1.z, b1.w, b2.x, b2.y, b2.z, b2.w};
    float o[8];
    #pragma unroll
    for (int j = 0; j < 8; j++) o[j] = (v[j] - mu) * rstd * gv[j] + bvv[j];
    float* orow = out + (size_t)row * C + lane * 8;
    *(float4*)(orow) = make_float4(o[0], o[1], o[2], o[3]);
    *(float4*)(orow + 4) = make_float4(o[4], o[5], o[6], o[7]);
}

// ---------------------------------------------------------------------------
extern "C" void kernel_launch(void* const* d_in, const int* in_sizes, int n_in,
                              void* d_out, int out_size) {
    const float* x     = (const float*)d_in[0];
    const int*   src   = (const int*)d_in[1];
    const int*   dst   = (const int*)d_in[2];
    const float* Wq    = (const float*)d_in[3];
    const float* bq    = (const float*)d_in[4];
    const float* Wk    = (const float*)d_in[5];
    const float* bk    = (const float*)d_in[6];
    const float* Wv    = (const float*)d_in[7];
    const float* bv    = (const float*)d_in[8];
    const float* spd_w = (const float*)d_in[9];
    const float* gamma = (const float*)d_in[10];
    const float* beta  = (const float*)d_in[11];
    float* out = (float*)d_out;

    int n = in_sizes[0] / C;
    int e = in_sizes[1];

    k_init<<<(n + 255) / 256, 256>>>(n);
    k_hist<<<HB, 256>>>(src, dst, e);
    k_prefix<<<1, 256>>>();
    k_bfs<<<1, 256>>>(src, dst);
    k_scatter<<<HB, 256>>>(src, dst, e);
    k_qu<<<NUM_DST, 256>>>(x, Wq, bq, Wk, bk);
    k_attn<<<NUM_DST, AT>>>(x, Wv, bv, spd_w);
    k_ln<<<(n + 7) / 8, 256>>>(x, gamma, beta, out, n);
}

// round 8
// speedup vs baseline: 1.0426x; 1.0426x over previous
#include <cuda_runtime.h>

#define C 256
#define H 8
#define NUM_DST 256
#define NMAX 50000
#define EMAX 300000
#define LISTCAP 8192
#define BCAP 4096         // smem-resident BFS edge cap (expected ~1536)
#define HB 512            // histogram/scatter blocks
#define INV_SQRT_DH 0.17677669529663687f
#define LN_EPS 1e-5f
#define AW 8              // warps per attention block
#define AT (AW * 32)

typedef unsigned long long u64;

__device__ int g_deg[NMAX];
__device__ int g_bcount[NUM_DST];
__device__ int g_bstart[NUM_DST];
__device__ int g_blockhist[HB * NUM_DST];
__device__ int g_blockbase[HB * NUM_DST];
__device__ int g_listcount;
__device__ int g_list[LISTCAP];
__device__ unsigned char g_spd[EMAX];
__device__ int g_sedge[EMAX];        // packed: src | (spd << 16), dst-bucket order
__device__ float g_u[NUM_DST * H * C];
__device__ float g_c0[NUM_DST * H];
__device__ float g_outsmall[NUM_DST * C];

// ---- f32x2 packed helpers --------------------------------------------------
__device__ __forceinline__ u64 pack2(float lo, float hi) {
    u64 r; asm("mov.b64 %0, {%1, %2};" : "=l"(r) : "f"(lo), "f"(hi)); return r;
}
__device__ __forceinline__ void unpack2(u64 v, float& lo, float& hi) {
    asm("mov.b64 {%0, %1}, %2;" : "=f"(lo), "=f"(hi) : "l"(v));
}
__device__ __forceinline__ void fma2(u64& d, u64 a, u64 b) {
    asm("fma.rn.f32x2 %0, %1, %2, %3;" : "=l"(d) : "l"(a), "l"(b), "l"(d));
}

// ---------------------------------------------------------------------------
// K0: init (deg + list counter only; spd handled inside k_bfs)
__global__ void k_init(int n) {
    int i = blockIdx.x * blockDim.x + threadIdx.x;
    if (i < n) g_deg[i] = 0;
    if (i == 0) g_listcount = 0;
}

// ---------------------------------------------------------------------------
// K1: block-local histograms + out-degree + src<256 list
__global__ void k_hist(const int* __restrict__ src, const int* __restrict__ dst, int e) {
    __shared__ int hist[NUM_DST];
    int t = threadIdx.x;
    hist[t] = 0;
    __syncthreads();
    for (int i = blockIdx.x * blockDim.x + t; i < e; i += gridDim.x * blockDim.x) {
        int s = src[i], d = dst[i];
        atomicAdd(&g_deg[s], 1);
        atomicAdd(&hist[d], 1);
        if (s < NUM_DST) {
            int p = atomicAdd(&g_listcount, 1);
            if (p < LISTCAP) g_list[p] = i;
        }
    }
    __syncthreads();
    g_blockhist[blockIdx.x * NUM_DST + t] = hist[t];
}

// ---------------------------------------------------------------------------
// K2: bucket totals, global scan, per-block bases, in-degree fold
__global__ void k_prefix() {
    __shared__ int tmp[NUM_DST];
    int t = threadIdx.x;
    int total = 0;
    for (int b = 0; b < HB; b++) total += g_blockhist[b * NUM_DST + t];
    tmp[t] = total;
    __syncthreads();
    for (int off = 1; off < NUM_DST; off <<= 1) {
        int v = (t >= off) ? tmp[t - off] : 0;
        __syncthreads();
        tmp[t] += v;
        __syncthreads();
    }
    int excl = tmp[t] - total;
    g_bstart[t] = excl;
    g_bcount[t] = total;
    g_deg[t] += total;  // in-degree (all dst < 256)
    int run = excl;
    for (int b = 0; b < HB; b++) {
        g_blockbase[b * NUM_DST + t] = run;
        run += g_blockhist[b * NUM_DST + t];
    }
}

// ---------------------------------------------------------------------------
// K3: reverse-BFS spd buckets, fully smem-resident. Listed edges have
// src<256 AND dst<256 -> pack into u16; per-edge spd lives in smem; one
// global write-back at the end. Overflow (>BCAP, ~never) uses the slow path.
__global__ void k_bfs(const int* __restrict__ src, const int* __restrict__ dst) {
    __shared__ unsigned F0[NUM_DST][8];
    __shared__ unsigned F1[NUM_DST][8];
    __shared__ unsigned short epk[BCAP];
    __shared__ unsigned char esp[BCAP];
    int t = threadIdx.x;
    #pragma unroll
    for (int w = 0; w < 8; w++)
        F0[t][w] = (w == (t >> 5)) ? (1u << (t & 31)) : 0u;
    int cnt = g_listcount;
    if (cnt > LISTCAP) cnt = LISTCAP;
    int scnt = cnt < BCAP ? cnt : BCAP;
    for (int i = t; i < scnt; i += 256) {
        int e = g_list[i];
        epk[i] = (unsigned short)(src[e] | (dst[e] << 8));
        esp[i] = 4;
    }
    for (int i = BCAP + t; i < cnt; i += 256) g_spd[g_list[i]] = 4;
    __syncthreads();
    for (int k = 1; k <= 3; k++) {
        #pragma unroll
        for (int w = 0; w < 8; w++) F1[t][w] = 0u;
        __syncthreads();
        for (int i = t; i < scnt; i += 256) {
            int p = epk[i];
            int s = p & 255, d = p >> 8;
            #pragma unroll
            for (int w = 0; w < 8; w++) {
                unsigned v = F0[s][w];
                if (v) atomicOr(&F1[d][w], v);
            }
        }
        for (int i = BCAP + t; i < cnt; i += 256) {
            int e = g_list[i];
            int s = src[e], d = dst[e];
            #pragma unroll
            for (int w = 0; w < 8; w++) {
                unsigned v = F0[s][w];
                if (v) atomicOr(&F1[d][w], v);
            }
        }
        __syncthreads();
        for (int i = t; i < scnt; i += 256) {
            int p = epk[i];
            int s = p & 255, d = p >> 8;
            if (esp[i] == 4 && ((F1[s][d >> 5] >> (d & 31)) & 1u))
                esp[i] = (unsigned char)k;
        }
        for (int i = BCAP + t; i < cnt; i += 256) {
            int e = g_list[i];
            int s = src[e], d = dst[e];
            if (g_spd[e] == 4 && ((F1[s][d >> 5] >> (d & 31)) & 1u))
                g_spd[e] = (unsigned char)k;
        }
        __syncthreads();
        #pragma unroll
        for (int w = 0; w < 8; w++) F0[t][w] = F1[t][w];
        __syncthreads();
    }
    for (int i = t; i < scnt; i += 256) g_spd[g_list[i]] = esp[i];
}

// ---------------------------------------------------------------------------
// K4: scatter with smem cursors; packs (src, spd) into one int
__global__ void k_scatter(const int* __restrict__ src, const int* __restrict__ dst, int e) {
    __shared__ int cur[NUM_DST];
    int t = threadIdx.x;
    cur[t] = g_blockbase[blockIdx.x * NUM_DST + t];
    __syncthreads();
    for (int i = blockIdx.x * blockDim.x + t; i < e; i += gridDim.x * blockDim.x) {
        int s = src[i], d = dst[i];
        int p = atomicAdd(&cur[d], 1);
        int sp = (s < NUM_DST) ? (int)g_spd[i] : 4;
        g_sedge[p] = s | (sp << 16);   // s < 50000 < 2^16
    }
}

// ---------------------------------------------------------------------------
// K5: per-dst u/c0 precompute, pre-scaled by 1/sqrt(DH)
__global__ void k_qu(const float* __restrict__ x,
                     const float* __restrict__ Wq, const float* __restrict__ bq,
                     const float* __restrict__ Wk, const float* __restrict__ bk) {
    int d = blockIdx.x;
    int t = threadIdx.x, lane = t & 31, wp = t >> 5;
    __shared__ float xs[C], qs[C];
    xs[t] = x[d * C + t];
    __syncthreads();
    for (int j = wp; j < C; j += 8) {
        const float* wr = Wq + j * C;
        float p = 0.f;
        #pragma unroll
        for (int i = 0; i < 8; i++) p += wr[lane + 32 * i] * xs[lane + 32 * i];
        #pragma unroll
        for (int o = 16; o; o >>= 1) p += __shfl_xor_sync(0xffffffffu, p, o);
        if (lane == 0) qs[j] = p + bq[j];
    }
    __syncthreads();
    #pragma unroll
    for (int h = 0; h < H; h++) {
        float acc = 0.f;
        #pragma unroll 8
        for (int j = 0; j < 32; j++)
            acc += qs[h * 32 + j] * Wk[(h * 32 + j) * C + t];
        g_u[d * H * C + h * C + t] = acc * INV_SQRT_DH;
    }
    if (t < H) {
        float s = 0.f;
        #pragma unroll
        for (int j = 0; j < 32; j++) s += qs[t * 32 + j] * bk[t * 32 + j];
        g_c0[d * H + t] = s * INV_SQRT_DH;
    }
}

// ---------------------------------------------------------------------------
// K6: per-dst fused attention. 8 warps, u AND accumulators in registers
// (zero smem in the edge loop), 2-deep software pipeline on the x-row gather,
// f32x2 packed FMAs, paired-warp STS epilogue (32 KB scratch, no atomics).
__global__ __launch_bounds__(AT, 1)
void k_attn(const float* __restrict__ x,
            const float* __restrict__ Wv, const float* __restrict__ bv,
            const float* __restrict__ spd_w) {
    int d = blockIdx.x;
    int t = threadIdx.x, lane = t & 31, wp = t >> 5;
    __shared__ __align__(16) float scratch[4][H * C];  // 32 KB
    __shared__ float csw[5 * H];
    __shared__ float lsh2[AW * H];
    __shared__ float Linv[H];

    if (t < 40) csw[t] = g_c0[d * H + (t & 7)] + spd_w[t];

    // u[d] into registers: 8 heads x 8 channels per lane (64 regs)
    u64 ur[H][4];
    const float* ubase = g_u + d * (H * C) + lane * 8;
    #pragma unroll
    for (int h = 0; h < H; h++) {
        ulonglong2 p0 = *(const ulonglong2*)(ubase + h * C);
        ulonglong2 p1 = *(const ulonglong2*)(ubase + h * C + 4);
        ur[h][0] = p0.x; ur[h][1] = p0.y; ur[h][2] = p1.x; ur[h][3] = p1.y;
    }

    int start = g_bstart[d], cnt = g_bcount[d];
    if (cnt == 0) {
        for (int i = t; i < C; i += AT) g_outsmall[d * C + i] = 0.f;
        return;
    }
    int end = start + cnt;
    int myh = (lane >> 2) & 7;
    unsigned b4 = (lane >> 4) & 1, b3 = (lane >> 3) & 1, b2 = (lane >> 2) & 1;

    u64 acc2[H][4];
    #pragma unroll
    for (int h = 0; h < H; h++)
        #pragma unroll
        for (int j = 0; j < 4; j++) acc2[h][j] = 0ull;
    float lsum = 0.f;

    // software pipeline: edge record + x row prefetched one iteration ahead
    int i = start + wp;
    int v0 = (i < end) ? g_sedge[i] : 0;
    const float4* xr0 = (const float4*)(x + (v0 & 0xFFFF) * C) + lane * 2;
    float4 a = xr0[0];
    float4 b = xr0[1];

    for (; i < end; i += AW) {
        int v1 = ((i + AW) < end) ? g_sedge[i + AW] : 0;
        const float4* xr1 = (const float4*)(x + (v1 & 0xFFFF) * C) + lane * 2;
        float4 na = xr1[0];
        float4 nb = xr1[1];
        int sp = v0 >> 16;

        u64 xv2[4];
        xv2[0] = pack2(a.x, a.y); xv2[1] = pack2(a.z, a.w);
        xv2[2] = pack2(b.x, b.y); xv2[3] = pack2(b.z, b.w);

        // per-head partial dot over this lane's 8 channels (register u)
        float p[H];
        #pragma unroll
        for (int h = 0; h < H; h++) {
            u64 q2 = 0ull;
            fma2(q2, xv2[0], ur[h][0]);
            fma2(q2, xv2[1], ur[h][1]);
            fma2(q2, xv2[2], ur[h][2]);
            fma2(q2, xv2[3], ur[h][3]);
            float lo, hi; unpack2(q2, lo, hi);
            p[h] = lo + hi;
        }

        // head-folding butterfly: 9 shfls total
        float r4[4];
        #pragma unroll
        for (int j = 0; j < 4; j++) {
            float mine = b4 ? p[j + 4] : p[j];
            float send = b4 ? p[j] : p[j + 4];
            r4[j] = mine + __shfl_xor_sync(0xffffffffu, send, 16);
        }
        float r2[2];
        #pragma unroll
        for (int j = 0; j < 2; j++) {
            float mine = b3 ? r4[j + 2] : r4[j];
            float send = b3 ? r4[j] : r4[j + 2];
            r2[j] = mine + __shfl_xor_sync(0xffffffffu, send, 8);
        }
        {
            float mine = b2 ? r2[1] : r2[0];
            float send = b2 ? r2[0] : r2[1];
            r2[0] = mine + __shfl_xor_sync(0xffffffffu, send, 4);
        }
        r2[0] += __shfl_xor_sync(0xffffffffu, r2[0], 2);
        r2[0] += __shfl_xor_sync(0xffffffffu, r2[0], 1);
        // lane holds full score for head myh

        float wv = __expf(r2[0] + csw[sp * H + myh]);
        lsum += wv;

        #pragma unroll
        for (int h = 0; h < H; h++) {
            float wh = __shfl_sync(0xffffffffu, wv, h * 4);
            u64 w2 = pack2(wh, wh);
            fma2(acc2[h][0], w2, xv2[0]);
            fma2(acc2[h][1], w2, xv2[1]);
            fma2(acc2[h][2], w2, xv2[2]);
            fma2(acc2[h][3], w2, xv2[3]);
        }

        v0 = v1; a = na; b = nb;
    }

    // epilogue: paired-warp combine into 4 smem slices, then tree reduce
    if ((lane & 3) == 0) lsh2[wp * H + myh] = lsum;
    if (wp >= 4) {
        #pragma unroll
        for (int h = 0; h < H; h++) {
            u64* dp = (u64*)&scratch[wp - 4][h * C + lane * 8];
            dp[0] = acc2[h][0]; dp[1] = acc2[h][1];
            dp[2] = acc2[h][2]; dp[3] = acc2[h][3];
        }
    }
    __syncthreads();
    if (wp < 4) {
        #pragma unroll
        for (int h = 0; h < H; h++) {
            u64* dp = (u64*)&scratch[wp][h * C + lane * 8];
            u64 s0 = dp[0], s1 = dp[1], s2 = dp[2], s3 = dp[3];
            fma2(s0, pack2(1.f, 1.f), acc2[h][0]);
            fma2(s1, pack2(1.f, 1.f), acc2[h][1]);
            fma2(s2, pack2(1.f, 1.f), acc2[h][2]);
            fma2(s3, pack2(1.f, 1.f), acc2[h][3]);
            dp[0] = s0; dp[1] = s1; dp[2] = s2; dp[3] = s3;
        }
    }
    if (t < H) {
        float L = 0.f;
        #pragma unroll
        for (int w = 0; w < AW; w++) L += lsh2[w * H + t];
        Linv[t] = 1.f / L;
    }
    __syncthreads();
    for (int idx = t; idx < H * C; idx += AT) {
        float s = scratch[0][idx] + scratch[1][idx] + scratch[2][idx] + scratch[3][idx];
        scratch[0][idx] = s * Linv[idx >> 8];
    }
    __syncthreads();

    // out[c] = agg[c/32] . Wv[c,:] + bv[c] ; 8 warps x 32 outputs
    for (int r = 0; r < C / AW; r++) {
        int c = wp * (C / AW) + r;
        int h = c >> 5;
        const float4* wr = (const float4*)(Wv + c * C) + lane * 2;
        float4 wa = wr[0], wb = wr[1];
        const float* ar = &scratch[0][h * C + lane * 8];
        float pacc = wa.x * ar[0] + wa.y * ar[1] + wa.z * ar[2] + wa.w * ar[3]
                   + wb.x * ar[4] + wb.y * ar[5] + wb.z * ar[6] + wb.w * ar[7];
        #pragma unroll
        for (int o = 16; o; o >>= 1) pacc += __shfl_xor_sync(0xffffffffu, pacc, o);
        if (lane == 0) g_outsmall[d * C + c] = pacc + bv[c];
    }
}

// ---------------------------------------------------------------------------
// K7: residual + degree + LayerNorm, one warp per row
__global__ void k_ln(const float* __restrict__ x,
                     const float* __restrict__ gamma, const float* __restrict__ beta,
                     float* __restrict__ out, int n) {
    int row = blockIdx.x * 8 + (threadIdx.x >> 5);
    int lane = threadIdx.x & 31;
    if (row >= n) return;
    const float* xr = x + (size_t)row * C + lane * 8;
    float4 a = *(const float4*)(xr);
    float4 b = *(const float4*)(xr + 4);
    float v[8] = {a.x, a.y, a.z, a.w, b.x, b.y, b.z, b.w};
    float degf = (float)g_deg[row];
    #pragma unroll
    for (int j = 0; j < 8; j++) v[j] += degf;
    if (row < NUM_DST) {
        const float* orow = g_outsmall + row * C + lane * 8;
        float4 oa = *(const float4*)(orow);
        float4 ob = *(const float4*)(orow + 4);
        v[0] += oa.x; v[1] += oa.y; v[2] += oa.z; v[3] += oa.w;
        v[4] += ob.x; v[5] += ob.y; v[6] += ob.z; v[7] += ob.w;
    }
    float s = 0.f;
    #pragma unroll
    for (int j = 0; j < 8; j++) s += v[j];
    #pragma unroll
    for (int o = 16; o; o >>= 1) s += __shfl_xor_sync(0xffffffffu, s, o);
    float mu = s * (1.f / C);
    float q = 0.f;
    #pragma unroll
    for (int j = 0; j < 8; j++) { float dd = v[j] - mu; q += dd * dd; }
    #pragma unroll
    for (int o = 16; o; o >>= 1) q += __shfl_xor_sync(0xffffffffu, q, o);
    float rstd = rsqrtf(q * (1.f / C) + LN_EPS);
    const float* gr = gamma + lane * 8;
    const float* br = beta + lane * 8;
    float4 g1 = *(const float4*)(gr);
    float4 g2 = *(const float4*)(gr + 4);
    float4 b1 = *(const float4*)(br);
    float4 b2 = *(const float4*)(br + 4);
    float gv[8] = {g1.x, g1.y, g1.z, g1.w, g2.x, g2.y, g2.z, g2.w};
    float bvv[8] = {b1.x, b1.y, b1.z, b1.w, b2.x, b2.y, b2.z, b2.w};
    float o[8];
    #pragma unroll
    for (int j = 0; j < 8; j++) o[j] = (v[j] - mu) * rstd * gv[j] + bvv[j];
    float* orow = out + (size_t)row * C + lane * 8;
    *(float4*)(orow) = make_float4(o[0], o[1], o[2], o[3]);
    *(float4*)(orow + 4) = make_float4(o[4], o[5], o[6], o[7]);
}

// ---------------------------------------------------------------------------
extern "C" void kernel_launch(void* const* d_in, const int* in_sizes, int n_in,
                              void* d_out, int out_size) {
    const float* x     = (const float*)d_in[0];
    const int*   src   = (const int*)d_in[1];
    const int*   dst   = (const int*)d_in[2];
    const float* Wq    = (const float*)d_in[3];
    const float* bq    = (const float*)d_in[4];
    const float* Wk    = (const float*)d_in[5];
    const float* bk    = (const float*)d_in[6];
    const float* Wv    = (const float*)d_in[7];
    const float* bv    = (const float*)d_in[8];
    const float* spd_w = (const float*)d_in[9];
    const float* gamma = (const float*)d_in[10];
    const float* beta  = (const float*)d_in[11];
    float* out = (float*)d_out;

    int n = in_sizes[0] / C;
    int e = in_sizes[1];

    k_init<<<(n + 255) / 256, 256>>>(n);
    k_hist<<<HB, 256>>>(src, dst, e);
    k_prefix<<<1, 256>>>();
    k_bfs<<<1, 256>>>(src, dst);
    k_scatter<<<HB, 256>>>(src, dst, e);
    k_qu<<<NUM_DST, 256>>>(x, Wq, bq, Wk, bk);
    k_attn<<<NUM_DST, AT>>>(x, Wv, bv, spd_w);
    k_ln<<<(n + 7) / 8, 256>>>(x, gamma, beta, out, n);
}

// round 9
// speedup vs baseline: 1.1716x; 1.1237x over previous
#include <cuda_runtime.h>

#define C 256
#define H 8
#define NUM_DST 256
#define NMAX 50000
#define EMAX 300000
#define LISTCAP 8192
#define BCAP 4096         // smem-resident BFS edge cap (expected ~1536)
#define HB 512            // histogram/scatter blocks
#define INV_SQRT_DH 0.17677669529663687f
#define LN_EPS 1e-5f
#define AW 4              // warps per attention block
#define AT (AW * 32)
#define SPLIT 4           // blocks per dst bucket
#define AGGSZ (NUM_DST * H * C)   // 524288

typedef unsigned long long u64;

__device__ int g_deg[NMAX];
__device__ int g_bcount[NUM_DST];
__device__ int g_bstart[NUM_DST];
__device__ int g_blockhist[HB * NUM_DST];
__device__ int g_blockbase[HB * NUM_DST];
__device__ int g_listcount;
__device__ int g_list[LISTCAP];
__device__ unsigned char g_spd[EMAX];
__device__ int g_sedge[EMAX];        // packed: src | (spd << 16), dst-bucket order
__device__ float g_u[NUM_DST * H * C];
__device__ float g_c0[NUM_DST * H];
__device__ float g_agg[AGGSZ];       // un-normalized per-dst per-head x aggregation
__device__ float g_l[NUM_DST * H];   // softmax denominators
__device__ float g_outsmall[NUM_DST * C];

// ---- f32x2 packed helpers --------------------------------------------------
__device__ __forceinline__ u64 pack2(float lo, float hi) {
    u64 r; asm("mov.b64 %0, {%1, %2};" : "=l"(r) : "f"(lo), "f"(hi)); return r;
}
__device__ __forceinline__ void unpack2(u64 v, float& lo, float& hi) {
    asm("mov.b64 {%0, %1}, %2;" : "=f"(lo), "=f"(hi) : "l"(v));
}
__device__ __forceinline__ void fma2(u64& d, u64 a, u64 b) {
    asm("fma.rn.f32x2 %0, %1, %2, %3;" : "=l"(d) : "l"(a), "l"(b), "l"(d));
}

// ---------------------------------------------------------------------------
// K0: init deg, list counter, agg/l accumulators
__global__ void k_init(int n) {
    int i = blockIdx.x * blockDim.x + threadIdx.x;
    if (i < n) g_deg[i] = 0;
    if (i < AGGSZ) g_agg[i] = 0.f;
    if (i < NUM_DST * H) g_l[i] = 0.f;
    if (i == 0) g_listcount = 0;
}

// ---------------------------------------------------------------------------
// K1: block-local histograms + out-degree + src<256 list
__global__ void k_hist(const int* __restrict__ src, const int* __restrict__ dst, int e) {
    __shared__ int hist[NUM_DST];
    int t = threadIdx.x;
    hist[t] = 0;
    __syncthreads();
    for (int i = blockIdx.x * blockDim.x + t; i < e; i += gridDim.x * blockDim.x) {
        int s = src[i], d = dst[i];
        atomicAdd(&g_deg[s], 1);
        atomicAdd(&hist[d], 1);
        if (s < NUM_DST) {
            int p = atomicAdd(&g_listcount, 1);
            if (p < LISTCAP) g_list[p] = i;
        }
    }
    __syncthreads();
    g_blockhist[blockIdx.x * NUM_DST + t] = hist[t];
}

// ---------------------------------------------------------------------------
// K2: bucket totals, global scan, per-block bases, in-degree fold
__global__ void k_prefix() {
    __shared__ int tmp[NUM_DST];
    int t = threadIdx.x;
    int total = 0;
    for (int b = 0; b < HB; b++) total += g_blockhist[b * NUM_DST + t];
    tmp[t] = total;
    __syncthreads();
    for (int off = 1; off < NUM_DST; off <<= 1) {
        int v = (t >= off) ? tmp[t - off] : 0;
        __syncthreads();
        tmp[t] += v;
        __syncthreads();
    }
    int excl = tmp[t] - total;
    g_bstart[t] = excl;
    g_bcount[t] = total;
    g_deg[t] += total;  // in-degree (all dst < 256)
    int run = excl;
    for (int b = 0; b < HB; b++) {
        g_blockbase[b * NUM_DST + t] = run;
        run += g_blockhist[b * NUM_DST + t];
    }
}

// ---------------------------------------------------------------------------
// K3: reverse-BFS spd buckets, smem CSR, NO atomics in the rounds.
// Thread t owns frontier row t. Listed edges (src<256, dst<256) go into a
// per-dst CSR built once in smem. Overflow beyond BCAP (never expected) is
// handled with atomicOr contributions after the owner writes.
__global__ void k_bfs(const int* __restrict__ src, const int* __restrict__ dst) {
    __shared__ unsigned F0[NUM_DST][8];
    __shared__ unsigned F1[NUM_DST][8];
    __shared__ unsigned short epk[BCAP];
    __shared__ unsigned char esp[BCAP];
    __shared__ unsigned char csrc[BCAP];
    __shared__ int cnt[NUM_DST];
    __shared__ int scan[NUM_DST];
    __shared__ int cur[NUM_DST];
    int t = threadIdx.x;
    #pragma unroll
    for (int w = 0; w < 8; w++)
        F0[t][w] = (w == (t >> 5)) ? (1u << (t & 31)) : 0u;
    cnt[t] = 0;
    __syncthreads();
    int total = g_listcount;
    if (total > LISTCAP) total = LISTCAP;
    int scnt = total < BCAP ? total : BCAP;
    for (int i = t; i < scnt; i += 256) {
        int e = g_list[i];
        int s = src[e], d = dst[e];
        epk[i] = (unsigned short)(s | (d << 8));
        esp[i] = 4;
        atomicAdd(&cnt[d], 1);
    }
    for (int i = BCAP + t; i < total; i += 256) g_spd[g_list[i]] = 4;
    __syncthreads();
    // prefix sum of cnt -> scan (exclusive)
    int myc = cnt[t];
    scan[t] = myc;
    __syncthreads();
    for (int off = 1; off < NUM_DST; off <<= 1) {
        int v = (t >= off) ? scan[t - off] : 0;
        __syncthreads();
        scan[t] += v;
        __syncthreads();
    }
    int base = scan[t] - myc;
    cur[t] = base;
    __syncthreads();
    for (int i = t; i < scnt; i += 256) {
        int p = epk[i];
        int d = p >> 8;
        int q = atomicAdd(&cur[d], 1);
        csrc[q] = (unsigned char)(p & 255);
    }
    __syncthreads();
    for (int k = 1; k <= 3; k++) {
        // owner thread t computes F1[t] = OR of F0[src] over its incoming edges
        unsigned f0v = 0, f1v = 0, f2v = 0, f3v = 0, f4v = 0, f5v = 0, f6v = 0, f7v = 0;
        for (int j = base; j < base + myc; j++) {
            int s = csrc[j];
            f0v |= F0[s][0]; f1v |= F0[s][1]; f2v |= F0[s][2]; f3v |= F0[s][3];
            f4v |= F0[s][4]; f5v |= F0[s][5]; f6v |= F0[s][6]; f7v |= F0[s][7];
        }
        F1[t][0] = f0v; F1[t][1] = f1v; F1[t][2] = f2v; F1[t][3] = f3v;
        F1[t][4] = f4v; F1[t][5] = f5v; F1[t][6] = f6v; F1[t][7] = f7v;
        __syncthreads();
        // overflow contributions (never expected)
        for (int i = BCAP + t; i < total; i += 256) {
            int e = g_list[i];
            int s = src[e], d = dst[e];
            #pragma unroll
            for (int w = 0; w < 8; w++) {
                unsigned v = F0[s][w];
                if (v) atomicOr(&F1[d][w], v);
            }
        }
        __syncthreads();
        // spd checks
        for (int i = t; i < scnt; i += 256) {
            int p = epk[i];
            int s = p & 255, d = p >> 8;
            if (esp[i] == 4 && ((F1[s][d >> 5] >> (d & 31)) & 1u))
                esp[i] = (unsigned char)k;
        }
        for (int i = BCAP + t; i < total; i += 256) {
            int e = g_list[i];
            int s = src[e], d = dst[e];
            if (g_spd[e] == 4 && ((F1[s][d >> 5] >> (d & 31)) & 1u))
                g_spd[e] = (unsigned char)k;
        }
        __syncthreads();
        #pragma unroll
        for (int w = 0; w < 8; w++) F0[t][w] = F1[t][w];
        __syncthreads();
    }
    for (int i = t; i < scnt; i += 256) g_spd[g_list[i]] = esp[i];
}

// ---------------------------------------------------------------------------
// K4: scatter with smem cursors; packs (src, spd) into one int
__global__ void k_scatter(const int* __restrict__ src, const int* __restrict__ dst, int e) {
    __shared__ int cur[NUM_DST];
    int t = threadIdx.x;
    cur[t] = g_blockbase[blockIdx.x * NUM_DST + t];
    __syncthreads();
    for (int i = blockIdx.x * blockDim.x + t; i < e; i += gridDim.x * blockDim.x) {
        int s = src[i], d = dst[i];
        int p = atomicAdd(&cur[d], 1);
        int sp = (s < NUM_DST) ? (int)g_spd[i] : 4;
        g_sedge[p] = s | (sp << 16);   // s < 50000 < 2^16
    }
}

// ---------------------------------------------------------------------------
// K5: per-dst u/c0 precompute, pre-scaled by 1/sqrt(DH)
__global__ void k_qu(const float* __restrict__ x,
                     const float* __restrict__ Wq, const float* __restrict__ bq,
                     const float* __restrict__ Wk, const float* __restrict__ bk) {
    int d = blockIdx.x;
    int t = threadIdx.x, lane = t & 31, wp = t >> 5;
    __shared__ float xs[C], qs[C];
    xs[t] = x[d * C + t];
    __syncthreads();
    for (int j = wp; j < C; j += 8) {
        const float* wr = Wq + j * C;
        float p = 0.f;
        #pragma unroll
        for (int i = 0; i < 8; i++) p += wr[lane + 32 * i] * xs[lane + 32 * i];
        #pragma unroll
        for (int o = 16; o; o >>= 1) p += __shfl_xor_sync(0xffffffffu, p, o);
        if (lane == 0) qs[j] = p + bq[j];
    }
    __syncthreads();
    #pragma unroll
    for (int h = 0; h < H; h++) {
        float acc = 0.f;
        #pragma unroll 8
        for (int j = 0; j < 32; j++)
            acc += qs[h * 32 + j] * Wk[(h * 32 + j) * C + t];
        g_u[d * H * C + h * C + t] = acc * INV_SQRT_DH;
    }
    if (t < H) {
        float s = 0.f;
        #pragma unroll
        for (int j = 0; j < 32; j++) s += qs[t * 32 + j] * bk[t * 32 + j];
        g_c0[d * H + t] = s * INV_SQRT_DH;
    }
}

// ---------------------------------------------------------------------------
// K6: fused attention partials. SPLIT blocks per dst (1024 blocks x 128 thr,
// occ 2 -> 256-reg cap, no spills). u + acc in registers, f32x2 FMAs,
// in-block smem tree then global REDG combine into g_agg / g_l.
__global__ __launch_bounds__(AT, 2)
void k_attn(const float* __restrict__ x, const float* __restrict__ spd_w) {
    int blk = blockIdx.x;
    int d = blk >> 2, seg = blk & 3;
    int t = threadIdx.x, lane = t & 31, wp = t >> 5;
    __shared__ __align__(16) float scratch[2][H * C];  // 16 KB
    __shared__ float csw[5 * H];
    __shared__ float lsh[AW * H];

    if (t < 40) csw[t] = g_c0[d * H + (t & 7)] + spd_w[t];

    // u[d] into registers: 8 heads x 8 channels per lane (64 regs)
    u64 ur[H][4];
    const float* ubase = g_u + d * (H * C) + lane * 8;
    #pragma unroll
    for (int h = 0; h < H; h++) {
        ulonglong2 p0 = *(const ulonglong2*)(ubase + h * C);
        ulonglong2 p1 = *(const ulonglong2*)(ubase + h * C + 4);
        ur[h][0] = p0.x; ur[h][1] = p0.y; ur[h][2] = p1.x; ur[h][3] = p1.y;
    }
    __syncthreads();

    int s0 = g_bstart[d], cnt = g_bcount[d];
    int b0 = s0 + (cnt * seg) / SPLIT;
    int b1 = s0 + (cnt * (seg + 1)) / SPLIT;

    int myh = (lane >> 2) & 7;
    unsigned b4 = (lane >> 4) & 1, b3 = (lane >> 3) & 1, b2 = (lane >> 2) & 1;

    u64 acc2[H][4];
    #pragma unroll
    for (int h = 0; h < H; h++)
        #pragma unroll
        for (int j = 0; j < 4; j++) acc2[h][j] = 0ull;
    float lsum = 0.f;

    // software pipeline: edge record + x row prefetched one iteration ahead
    int i = b0 + wp;
    int v0 = (i < b1) ? g_sedge[i] : 0;
    const float4* xr0 = (const float4*)(x + (v0 & 0xFFFF) * C) + lane * 2;
    float4 a, b;
    if (i < b1) { a = xr0[0]; b = xr0[1]; }

    for (; i < b1; i += AW) {
        int v1 = ((i + AW) < b1) ? g_sedge[i + AW] : 0;
        const float4* xr1 = (const float4*)(x + (v1 & 0xFFFF) * C) + lane * 2;
        float4 na, nb;
        if (i + AW < b1) { na = xr1[0]; nb = xr1[1]; }
        int sp = v0 >> 16;

        u64 xv2[4];
        xv2[0] = pack2(a.x, a.y); xv2[1] = pack2(a.z, a.w);
        xv2[2] = pack2(b.x, b.y); xv2[3] = pack2(b.z, b.w);

        // per-head partial dot over this lane's 8 channels (register u)
        float p[H];
        #pragma unroll
        for (int h = 0; h < H; h++) {
            u64 q2 = 0ull;
            fma2(q2, xv2[0], ur[h][0]);
            fma2(q2, xv2[1], ur[h][1]);
            fma2(q2, xv2[2], ur[h][2]);
            fma2(q2, xv2[3], ur[h][3]);
            float lo, hi; unpack2(q2, lo, hi);
            p[h] = lo + hi;
        }

        // head-folding butterfly: 9 shfls total
        float r4[4];
        #pragma unroll
        for (int j = 0; j < 4; j++) {
            float mine = b4 ? p[j + 4] : p[j];
            float send = b4 ? p[j] : p[j + 4];
            r4[j] = mine + __shfl_xor_sync(0xffffffffu, send, 16);
        }
        float r2[2];
        #pragma unroll
        for (int j = 0; j < 2; j++) {
            float mine = b3 ? r4[j + 2] : r4[j];
            float send = b3 ? r4[j] : r4[j + 2];
            r2[j] = mine + __shfl_xor_sync(0xffffffffu, send, 8);
        }
        {
            float mine = b2 ? r2[1] : r2[0];
            float send = b2 ? r2[0] : r2[1];
            r2[0] = mine + __shfl_xor_sync(0xffffffffu, send, 4);
        }
        r2[0] += __shfl_xor_sync(0xffffffffu, r2[0], 2);
        r2[0] += __shfl_xor_sync(0xffffffffu, r2[0], 1);
        // lane holds full score for head myh

        float wv = __expf(r2[0] + csw[sp * H + myh]);
        lsum += wv;

        #pragma unroll
        for (int h = 0; h < H; h++) {
            float wh = __shfl_sync(0xffffffffu, wv, h * 4);
            u64 w2 = pack2(wh, wh);
            fma2(acc2[h][0], w2, xv2[0]);
            fma2(acc2[h][1], w2, xv2[1]);
            fma2(acc2[h][2], w2, xv2[2]);
            fma2(acc2[h][3], w2, xv2[3]);
        }

        v0 = v1; a = na; b = nb;
    }

    // epilogue: warps 2,3 store; warps 0,1 add; 128 threads REDG to global
    if ((lane & 3) == 0) lsh[wp * H + myh] = lsum;
    if (wp >= 2) {
        #pragma unroll
        for (int h = 0; h < H; h++) {
            u64* dp = (u64*)&scratch[wp - 2][h * C + lane * 8];
            dp[0] = acc2[h][0]; dp[1] = acc2[h][1];
            dp[2] = acc2[h][2]; dp[3] = acc2[h][3];
        }
    }
    __syncthreads();
    if (wp < 2) {
        #pragma unroll
        for (int h = 0; h < H; h++) {
            u64* dp = (u64*)&scratch[wp][h * C + lane * 8];
            u64 s0q = dp[0], s1q = dp[1], s2q = dp[2], s3q = dp[3];
            u64 one = pack2(1.f, 1.f);
            fma2(s0q, one, acc2[h][0]);
            fma2(s1q, one, acc2[h][1]);
            fma2(s2q, one, acc2[h][2]);
            fma2(s3q, one, acc2[h][3]);
            dp[0] = s0q; dp[1] = s1q; dp[2] = s2q; dp[3] = s3q;
        }
    }
    __syncthreads();
    float* gbase = g_agg + d * (H * C);
    for (int idx = t; idx < H * C; idx += AT)
        atomicAdd(&gbase[idx], scratch[0][idx] + scratch[1][idx]);
    if (t < H) {
        float L = lsh[t] + lsh[H + t] + lsh[2 * H + t] + lsh[3 * H + t];
        atomicAdd(&g_l[d * H + t], L);
    }
}

// ---------------------------------------------------------------------------
// K6b: normalize + V projection: out[c] = (agg[c/32]/L) . Wv[c,:] + bv[c]
__global__ void k_vproj(const float* __restrict__ Wv, const float* __restrict__ bv) {
    int d = blockIdx.x;
    int t = threadIdx.x, lane = t & 31, wp = t >> 5;
    __shared__ __align__(16) float agg[H * C];
    __shared__ float Linv[H];
    if (g_bcount[d] == 0) {
        g_outsmall[d * C + t] = 0.f;
        return;
    }
    if (t < H) Linv[t] = 1.f / g_l[d * H + t];
    __syncthreads();
    for (int idx = t; idx < H * C; idx += 256)
        agg[idx] = g_agg[d * (H * C) + idx] * Linv[idx >> 8];
    __syncthreads();
    for (int r = 0; r < 32; r++) {
        int c = wp * 32 + r;
        int h = c >> 5;
        const float4* wr = (const float4*)(Wv + c * C) + lane * 2;
        float4 wa = wr[0], wb = wr[1];
        const float* ar = &agg[h * C + lane * 8];
        float pacc = wa.x * ar[0] + wa.y * ar[1] + wa.z * ar[2] + wa.w * ar[3]
                   + wb.x * ar[4] + wb.y * ar[5] + wb.z * ar[6] + wb.w * ar[7];
        #pragma unroll
        for (int o = 16; o; o >>= 1) pacc += __shfl_xor_sync(0xffffffffu, pacc, o);
        if (lane == 0) g_outsmall[d * C + c] = pacc + bv[c];
    }
}

// ---------------------------------------------------------------------------
// K7: residual + degree + LayerNorm, one warp per row
__global__ void k_ln(const float* __restrict__ x,
                     const float* __restrict__ gamma, const float* __restrict__ beta,
                     float* __restrict__ out, int n) {
    int row = blockIdx.x * 8 + (threadIdx.x >> 5);
    int lane = threadIdx.x & 31;
    if (row >= n) return;
    const float* xr = x + (size_t)row * C + lane * 8;
    float4 a = *(const float4*)(xr);
    float4 b = *(const float4*)(xr + 4);
    float v[8] = {a.x, a.y, a.z, a.w, b.x, b.y, b.z, b.w};
    float degf = (float)g_deg[row];
    #pragma unroll
    for (int j = 0; j < 8; j++) v[j] += degf;
    if (row < NUM_DST) {
        const float* orow = g_outsmall + row * C + lane * 8;
        float4 oa = *(const float4*)(orow);
        float4 ob = *(const float4*)(orow + 4);
        v[0] += oa.x; v[1] += oa.y; v[2] += oa.z; v[3] += oa.w;
        v[4] += ob.x; v[5] += ob.y; v[6] += ob.z; v[7] += ob.w;
    }
    float s = 0.f;
    #pragma unroll
    for (int j = 0; j < 8; j++) s += v[j];
    #pragma unroll
    for (int o = 16; o; o >>= 1) s += __shfl_xor_sync(0xffffffffu, s, o);
    float mu = s * (1.f / C);
    float q = 0.f;
    #pragma unroll
    for (int j = 0; j < 8; j++) { float dd = v[j] - mu; q += dd * dd; }
    #pragma unroll
    for (int o = 16; o; o >>= 1) q += __shfl_xor_sync(0xffffffffu, q, o);
    float rstd = rsqrtf(q * (1.f / C) + LN_EPS);
    const float* gr = gamma + lane * 8;
    const float* br = beta + lane * 8;
    float4 g1 = *(const float4*)(gr);
    float4 g2 = *(const float4*)(gr + 4);
    float4 b1 = *(const float4*)(br);
    float4 b2 = *(const float4*)(br + 4);
    float gv[8] = {g1.x, g1.y, g1.z, g1.w, g2.x, g2.y, g2.z, g2.w};
    float bvv[8] = {b1.x, b1.y, b1.z, b1.w, b2.x, b2.y, b2.z, b2.w};
    float o[8];
    #pragma unroll
    for (int j = 0; j < 8; j++) o[j] = (v[j] - mu) * rstd * gv[j] + bvv[j];
    float* orow = out + (size_t)row * C + lane * 8;
    *(float4*)(orow) = make_float4(o[0], o[1], o[2], o[3]);
    *(float4*)(orow + 4) = make_float4(o[4], o[5], o[6], o[7]);
}

// ---------------------------------------------------------------------------
extern "C" void kernel_launch(void* const* d_in, const int* in_sizes, int n_in,
                              void* d_out, int out_size) {
    const float* x     = (const float*)d_in[0];
    const int*   src   = (const int*)d_in[1];
    const int*   dst   = (const int*)d_in[2];
    const float* Wq    = (const float*)d_in[3];
    const float* bq    = (const float*)d_in[4];
    const float* Wk    = (const float*)d_in[5];
    const float* bk    = (const float*)d_in[6];
    const float* Wv    = (const float*)d_in[7];
    const float* bv    = (const float*)d_in[8];
    const float* spd_w = (const float*)d_in[9];
    const float* gamma = (const float*)d_in[10];
    const float* beta  = (const float*)d_in[11];
    float* out = (float*)d_out;

    int n = in_sizes[0] / C;
    int e = in_sizes[1];
    int initN = (AGGSZ > n) ? AGGSZ : n;

    k_init<<<(initN + 255) / 256, 256>>>(n);
    k_hist<<<HB, 256>>>(src, dst, e);
    k_prefix<<<1, 256>>>();
    k_bfs<<<1, 256>>>(src, dst);
    k_scatter<<<HB, 256>>>(src, dst, e);
    k_qu<<<NUM_DST, 256>>>(x, Wq, bq, Wk, bk);
    k_attn<<<NUM_DST * SPLIT, AT>>>(x, spd_w);
    k_vproj<<<NUM_DST, 256>>>(Wv, bv);
    k_ln<<<(n + 7) / 8, 256>>>(x, gamma, beta, out, n);
}